// round 5
// baseline (speedup 1.0000x reference)
#include <cuda_runtime.h>
#include <stdint.h>

#define NUM_GRAPHS   4096
#define EMB_DIM      128
#define MAIN_THREADS 128
#define MAIN_BLOCKS  (152 * 12)   // GB300: 152 SMs x 12 blocks -> exactly one wave

__device__ float g_acc[NUM_GRAPHS * EMB_DIM];
__device__ float g_l[NUM_GRAPHS];
__device__ float g_cnt[NUM_GRAPHS];

__global__ void zero_kernel()
{
    const int i = blockIdx.x * blockDim.x + threadIdx.x;
    if (i < NUM_GRAPHS * EMB_DIM) g_acc[i] = 0.0f;
    if (i < NUM_GRAPHS) { g_l[i] = 0.0f; g_cnt[i] = 0.0f; }
}

__global__ __launch_bounds__(MAIN_THREADS, 12)
void att_partial_kernel(const float* __restrict__ x,
                        const void* __restrict__ batch_raw,
                        const float* __restrict__ w,
                        int n_nodes)
{
    const int t    = threadIdx.x;
    const int warp = t >> 5;
    const int lane = t & 31;

    const float4 wv = ((const float4*)w)[lane];

    // dtype probe: int32 -> last word is the max graph id (!=0);
    // int64 (values < 2^31, LE) -> word n-1 is an upper half (==0).
    const int*       b32 = (const int*)batch_raw;
    const long long* b64 = (const long long*)batch_raw;
    const bool is64 = (b32[n_nodes - 1] == 0);

    // balanced contiguous node ranges: block range -> warp quarter
    const int per_block = (n_nodes + MAIN_BLOCKS - 1) / MAIN_BLOCKS;
    const int bstart = blockIdx.x * per_block;
    const int bend   = min(n_nodes, bstart + per_block);
    if (bstart >= bend) return;
    const int per_warp = (bend - bstart + 3) >> 2;
    const int wstart = bstart + warp * per_warp;
    const int wend   = min(bend, wstart + per_warp);
    if (wstart >= wend) return;

    int    cur  = -1;
    float4 acc  = make_float4(0.f, 0.f, 0.f, 0.f);
    float  l    = 0.f;
    float  cntf = 0.f;

#define FLUSH() do {                                                        \
        if (cur >= 0 && cntf > 0.f) {                                      \
            float* dst = g_acc + (size_t)cur * EMB_DIM + lane * 4;         \
            atomicAdd(dst + 0, acc.x);                                     \
            atomicAdd(dst + 1, acc.y);                                     \
            atomicAdd(dst + 2, acc.z);                                     \
            atomicAdd(dst + 3, acc.w);                                     \
            if (lane == 0) {                                               \
                atomicAdd(&g_l[cur],   l);                                 \
                atomicAdd(&g_cnt[cur], cntf);                              \
            }                                                              \
        }                                                                  \
        acc = make_float4(0.f, 0.f, 0.f, 0.f); l = 0.f; cntf = 0.f;        \
    } while (0)

#define LOADROW(idx) (((const float4*)(x + (size_t)(idx) * EMB_DIM))[lane])
#define GID(idx)     (is64 ? (int)b64[idx] : b32[idx])

    int j = wstart;

    // prime double buffer: rows j, j+1 in flight
    float4 a0 = LOADROW(j);
    int    ga0 = GID(j);
    bool   h1 = (j + 1 < wend);
    float4 a1 = make_float4(0.f, 0.f, 0.f, 0.f);
    int    ga1 = 0;
    if (h1) { a1 = LOADROW(j + 1); ga1 = GID(j + 1); }

    while (true) {
        // issue NEXT pair's loads before touching the current pair
        const int jn = j + 2;
        const bool n0 = (jn     < wend);
        const bool n1 = (jn + 1 < wend);
        float4 nb0, nb1; int gb0 = 0, gb1 = 0;
        if (n0) { nb0 = LOADROW(jn);     gb0 = GID(jn);     }
        if (n1) { nb1 = LOADROW(jn + 1); gb1 = GID(jn + 1); }

        // compute current pair (overlaps with in-flight loads)
        float p0 = a0.x * wv.x + a0.y * wv.y + a0.z * wv.z + a0.w * wv.w;
        float p1 = h1 ? (a1.x * wv.x + a1.y * wv.y + a1.z * wv.z + a1.w * wv.w) : 0.f;
        #pragma unroll
        for (int o = 16; o; o >>= 1) {
            p0 += __shfl_xor_sync(0xffffffffu, p0, o);
            p1 += __shfl_xor_sync(0xffffffffu, p1, o);
        }
        const float e0 = __expf(p0);
        const float e1 = __expf(p1);

        // no-max softmax (shift-invariant; |score| small enough for fp32 exp)
        if (ga0 != cur) { FLUSH(); cur = ga0; }
        acc.x += e0 * a0.x; acc.y += e0 * a0.y;
        acc.z += e0 * a0.z; acc.w += e0 * a0.w;
        l += e0; cntf += 1.f;
        if (h1) {
            if (ga1 != cur) { FLUSH(); cur = ga1; }
            acc.x += e1 * a1.x; acc.y += e1 * a1.y;
            acc.z += e1 * a1.z; acc.w += e1 * a1.w;
            l += e1; cntf += 1.f;
        }

        if (!n0) break;
        a0 = nb0; ga0 = gb0;
        h1 = n1;
        if (n1) { a1 = nb1; ga1 = gb1; }
        j = jn;
    }
    FLUSH();

#undef FLUSH
#undef LOADROW
#undef GID
}

__global__ void finalize_kernel(const float* __restrict__ w,
                                float* __restrict__ out,
                                int out_size)
{
    const int i = blockIdx.x * blockDim.x + threadIdx.x;
    if (i < NUM_GRAPHS * EMB_DIM) {
        const int g = i >> 7;
        const float denom = fmaxf(g_l[g], 1e-30f) * fmaxf(g_cnt[g], 1.0f);
        out[i] = g_acc[i] / denom;
    }
    if (i < EMB_DIM && out_size >= NUM_GRAPHS * EMB_DIM + EMB_DIM)
        out[NUM_GRAPHS * EMB_DIM + i] = w[i];
}

extern "C" void kernel_launch(void* const* d_in, const int* in_sizes, int n_in,
                              void* d_out, int out_size)
{
    const float* x     = (const float*)d_in[0];
    const void*  batch = d_in[1];
    const float* w     = (const float*)d_in[2];
    float*       out   = (float*)d_out;
    const int n_nodes  = in_sizes[1];

    zero_kernel<<<(NUM_GRAPHS * EMB_DIM + 255) / 256, 256>>>();
    att_partial_kernel<<<MAIN_BLOCKS, MAIN_THREADS>>>(x, batch, w, n_nodes);
    finalize_kernel<<<(NUM_GRAPHS * EMB_DIM + 255) / 256, 256>>>(w, out, out_size);
}

// round 6
// speedup vs baseline: 1.4965x; 1.4965x over previous
#include <cuda_runtime.h>
#include <stdint.h>

#define NUM_GRAPHS 4096
#define EMB_DIM 128
#define THREADS 128
#define DEPTH 4          // per-warp cp.async ring depth (rows in flight)

__global__ __launch_bounds__(THREADS)
void att_pool_kernel(const float* __restrict__ x,
                     const void* __restrict__ batch_raw,
                     const float* __restrict__ w,
                     float* __restrict__ out,
                     int n_nodes, int out_size)
{
    const int t    = threadIdx.x;
    const int g    = blockIdx.x;
    const int warp = t >> 5;
    const int lane = t & 31;

    __shared__ float4 buf[4][DEPTH][32];   // 8 KB ring: [warp][slot][lane]
    __shared__ float  accs[4][EMB_DIM];
    __shared__ float  ls[4];
    __shared__ int    s_start, s_end;

    // Binary search contiguous [start,end) for graph g (batch sorted).
    // dtype probe: int32 -> word n-1 is the last graph id (!=0);
    // int64 (values < 2^31, LE) -> word n-1 is an upper half (==0).
    if (t == 0) {
        const int*       b32 = (const int*)batch_raw;
        const long long* b64 = (const long long*)batch_raw;
        const bool is64 = (b32[n_nodes - 1] == 0);

        long long gv = (long long)g;
        int lo = 0, hi = n_nodes;
        while (lo < hi) {
            int mid = (lo + hi) >> 1;
            long long v = is64 ? b64[mid] : (long long)b32[mid];
            if (v < gv) lo = mid + 1; else hi = mid;
        }
        s_start = lo;
        hi = n_nodes;
        const long long gv1 = gv + 1;
        while (lo < hi) {
            int mid = (lo + hi) >> 1;
            long long v = is64 ? b64[mid] : (long long)b32[mid];
            if (v < gv1) lo = mid + 1; else hi = mid;
        }
        s_end = lo;
    }

    const float4 wv = ((const float4*)w)[lane];
    __syncthreads();

    const int start = s_start;
    const int end   = s_end;
    const int cnt   = end - start;

    // Warp handles rows start+warp, start+warp+4, ... (contiguous lane float4s).
    int nrows = 0;
    if (end - start > warp) nrows = (end - start - warp + 3) >> 2;

    const float* base = x + (size_t)(start + warp) * EMB_DIM + lane * 4;
    const uint32_t sbase = (uint32_t)__cvta_generic_to_shared(&buf[warp][0][lane]);
    // slot stride in bytes: 32 lanes * 16 B = 512

    // ---- prologue: fill the ring (one commit group per row, empty groups ok) ----
    #pragma unroll
    for (int d = 0; d < DEPTH; d++) {
        if (d < nrows) {
            const float* src = base + (size_t)d * 4 * EMB_DIM;
            asm volatile("cp.async.cg.shared.global [%0], [%1], 16;\n"
                         :: "r"(sbase + d * 512), "l"(src));
        }
        asm volatile("cp.async.commit_group;\n");
    }

    // ---- main loop: wait oldest group, consume, refill slot ----
    float4 acc = make_float4(0.f, 0.f, 0.f, 0.f);
    float  l   = 0.f;
    int slot = 0;

    for (int i = 0; i < nrows; i++) {
        asm volatile("cp.async.wait_group %0;\n" :: "n"(DEPTH - 1));
        const float4 xv = buf[warp][slot][lane];

        // refill the slot with row i+DEPTH (write lands >=300cyc after the LDS above)
        const int nr = i + DEPTH;
        if (nr < nrows) {
            const float* src = base + (size_t)nr * 4 * EMB_DIM;
            asm volatile("cp.async.cg.shared.global [%0], [%1], 16;\n"
                         :: "r"(sbase + slot * 512), "l"(src));
        }
        asm volatile("cp.async.commit_group;\n");

        // score -> warp reduce -> exp -> accumulate (no-max softmax: shift-invariant)
        float p = xv.x * wv.x + xv.y * wv.y + xv.z * wv.z + xv.w * wv.w;
        #pragma unroll
        for (int o = 16; o; o >>= 1) p += __shfl_xor_sync(0xffffffffu, p, o);
        const float e = __expf(p);
        acc.x += e * xv.x; acc.y += e * xv.y;
        acc.z += e * xv.z; acc.w += e * xv.w;
        l += e;

        slot = (slot + 1) & (DEPTH - 1);
    }

    // ---- combine 4 warps ----
    ((float4*)accs[warp])[lane] = acc;
    if (lane == 0) ls[warp] = l;
    __syncthreads();

    const float a = accs[0][t] + accs[1][t] + accs[2][t] + accs[3][t];
    const float L = ls[0] + ls[1] + ls[2] + ls[3];

    const float denom = fmaxf(L, 1e-30f) * fmaxf((float)cnt, 1.0f);
    out[(size_t)g * EMB_DIM + t] = a / denom;

    if (g == 0 && out_size >= NUM_GRAPHS * EMB_DIM + EMB_DIM) {
        out[NUM_GRAPHS * EMB_DIM + t] = w[t];
    }
}

extern "C" void kernel_launch(void* const* d_in, const int* in_sizes, int n_in,
                              void* d_out, int out_size)
{
    const float* x     = (const float*)d_in[0];
    const void*  batch = d_in[1];
    const float* w     = (const float*)d_in[2];
    float*       out   = (float*)d_out;
    const int n_nodes  = in_sizes[1];

    att_pool_kernel<<<NUM_GRAPHS, THREADS>>>(x, batch, w, out, n_nodes, out_size);
}